// round 12
// baseline (speedup 1.0000x reference)
#include <cuda_runtime.h>

#define THREADS 512
#define BINS 256
#define NBLOCKS (148 * 4)       // 4 blocks/SM x 512 threads = 2048 threads/SM
#define ROUNDS 8                // depth-3 rounds per ticket
#define TILE_V (32 * 3 * ROUNDS) // 768 float4 = 12KB per warp-ticket

// Zero-initialized device scratch. The last block re-zeroes everything each
// call, so every graph replay sees identical initial state. Ticket->warp
// assignment is nondeterministic but integer-count summation is
// order-independent -> bit-identical output every run.
__device__ unsigned int g_partial[BINS];
__device__ unsigned int g_ticket;
__device__ unsigned int g_tile;

// Histogram layout h[bin][lane]: lane l only touches column l -> every
// warp-ATOMS hits 32 DISTINCT banks. Structurally conflict-free shared
// atomics (proven R7: L1% 63->33, dur 51.7->47.2).
__device__ __forceinline__ void bin_one(float f, unsigned int* hl) {
    // torch.histc: bins over [-4,4], x==4 -> last bin, outside ignored.
    // (f+4)*32 == fmaf(f,32,128) bit-exactly (x32 is an exact binade shift).
    if (fabsf(f) <= 4.0f) {
        int b = __float2int_rd(fmaf(f, 32.0f, 128.0f));
        b = min(b, BINS - 1);
        atomicAdd(&hl[b << 5], 1u);   // hl already offset by lane
    }
}

__device__ __forceinline__ void bin4(float4 v, unsigned int* hl) {
    bin_one(v.x, hl);
    bin_one(v.y, hl);
    bin_one(v.z, hl);
    bin_one(v.w, hl);
}

__global__ __launch_bounds__(THREADS) void histc_kernel(
    const float4* __restrict__ x, float* __restrict__ out, int n4, int dup)
{
    __shared__ unsigned int h[BINS * 32];   // 32 KB: h[b*32 + lane]
    __shared__ bool is_last;

    #pragma unroll
    for (int i = threadIdx.x; i < BINS * 32; i += THREADS)
        h[i] = 0u;
    __syncthreads();

    const int lane = threadIdx.x & 31;
    unsigned int* hl = &h[lane];
    const unsigned int ntiles = (unsigned int)((n4 + TILE_V - 1) / TILE_V);

    // Warp-autonomous dynamic scheduler: NO block barriers in the main loop
    // (R11 showed per-tile __syncthreads drains the load pipeline, DRAM
    // 75->70%). Lane 0 takes a ticket, shfl-broadcasts it; the next ticket is
    // prefetched at tile start so ATOMG latency (~318cyc) hides under the 8
    // rounds of work. 12KB tickets -> ~22K ATOMGs total, ~19K cyc at the LTS
    // atomic unit: not a bottleneck.
    unsigned int t = 0;
    if (lane == 0)
        t = atomicAdd(&g_tile, 1u);
    t = __shfl_sync(0xFFFFFFFFu, t, 0);

    while (t < ntiles) {
        unsigned int nt = 0;
        if (lane == 0)
            nt = atomicAdd(&g_tile, 1u);     // prefetch next ticket
        nt = __shfl_sync(0xFFFFFFFFu, nt, 0);

        int base = (int)t * TILE_V + lane;
        if ((int)(t + 1) * TILE_V <= n4) {
            // Full tile: ROUNDS x (3 front-batched 16B loads + binning).
            // unroll 1 keeps MLP_p1=3 in SASS (R4: MLP_p1=4+ at this occ
            // overflows the L1tex wavefront queue).
            #pragma unroll 1
            for (int r = 0; r < ROUNDS; r++) {
                int p = base + r * 96;       // 3*32 float4 per round
                float4 a = __ldcs(&x[p]);
                float4 b = __ldcs(&x[p + 32]);
                float4 c = __ldcs(&x[p + 64]);
                bin4(a, hl);
                bin4(b, hl);
                bin4(c, hl);
            }
        } else {
            for (int i = base; i < n4; i += 32)
                bin4(__ldcs(&x[i]), hl);
        }
        t = nt;
    }
    __syncthreads();

    // Reduce 32 lane-columns per bin. Diagonal read (start at own lane) keeps
    // all 32 lanes of a warp on distinct banks every step.
    if (threadIdx.x < BINS) {
        int b = threadIdx.x;
        unsigned int s = 0;
        #pragma unroll
        for (int k = 0; k < 32; k++)
            s += h[(b << 5) + ((k + lane) & 31)];
        if (s)
            atomicAdd(&g_partial[b], s);
    }

    // Last-block-done epilogue: final block writes both output copies and
    // resets all scratch. Plain stores overwrite the harness poison.
    __threadfence();
    if (threadIdx.x == 0) {
        unsigned int tk = atomicAdd(&g_ticket, 1u);
        is_last = (tk == (unsigned int)gridDim.x - 1u);
    }
    __syncthreads();

    if (is_last && threadIdx.x < BINS) {
        int b = threadIdx.x;
        unsigned int v = atomicAdd(&g_partial[b], 0u);  // L2-coherent read
        float fv = (float)v;
        out[b] = fv;
        if (dup)
            out[b + BINS] = fv;
        g_partial[b] = 0u;      // reset scratch for next graph replay
        if (b == 0) {
            g_ticket = 0u;
            g_tile = 0u;
        }
    }
}

extern "C" void kernel_launch(void* const* d_in, const int* in_sizes, int n_in,
                              void* d_out, int out_size)
{
    const float4* x = (const float4*)d_in[0];
    float* out = (float*)d_out;
    int n4 = in_sizes[0] / 4;
    int dup = (out_size >= 2 * BINS) ? 1 : 0;

    histc_kernel<<<NBLOCKS, THREADS>>>(x, out, n4, dup);
}

// round 13
// speedup vs baseline: 1.3270x; 1.3270x over previous
#include <cuda_runtime.h>

#define THREADS 512
#define BINS 256
#define NBLOCKS (148 * 4)   // 4 blocks/SM x 512 threads = 2048 threads/SM

// Zero-initialized device scratch. The last block re-zeroes it every call, so
// every graph replay sees identical initial state (deterministic).
__device__ unsigned int g_partial[BINS];
__device__ unsigned int g_ticket;

// Histogram layout h[bin][lane]: lane l only touches column l, so every
// warp-ATOMS hits 32 DISTINCT banks. Structurally conflict-free shared
// atomics (proven R7: L1% 63->33, dur 51.7->47.2).
__device__ __forceinline__ void bin_one(float f, unsigned int* hl) {
    // torch.histc: bins over [-4,4], x==4 -> last bin, outside ignored.
    // (f+4)*32 == fmaf(f,32,128) bit-exactly (x32 is an exact binade shift).
    if (fabsf(f) <= 4.0f) {
        int b = __float2int_rd(fmaf(f, 32.0f, 128.0f));
        b = min(b, BINS - 1);
        atomicAdd(&hl[b << 5], 1u);   // hl already offset by lane
    }
}

__device__ __forceinline__ void bin4(float4 v, unsigned int* hl) {
    bin_one(v.x, hl);
    bin_one(v.y, hl);
    bin_one(v.z, hl);
    bin_one(v.w, hl);
}

__global__ __launch_bounds__(THREADS) void histc_kernel(
    const float4* __restrict__ x, float* __restrict__ out, int n4, int dup)
{
    __shared__ unsigned int h[BINS * 32];   // 32 KB: h[b*32 + lane]
    __shared__ bool is_last;

    #pragma unroll
    for (int i = threadIdx.x; i < BINS * 32; i += THREADS)
        h[i] = 0u;
    __syncthreads();

    const int lane = threadIdx.x & 31;
    unsigned int* hl = &h[lane];

    const int stride = gridDim.x * blockDim.x;
    int i = blockIdx.x * blockDim.x + threadIdx.x;

    // Depth-3 CROSS-ITERATION software pipeline: binning of the current
    // triple overlaps the DRAM latency of the prefetched next triple.
    // (R12 proved that per-round load+consume without carry re-exposes the
    // full DRAM latency every round: 47->62us. R4 proved MLP_p1>=4 overflows
    // the L1tex wavefront queue at 2048 thr/SM: 52->72us.)
    if (i + 2 * stride < n4) {
        float4 a = __ldcs(&x[i]);
        float4 b = __ldcs(&x[i + stride]);
        float4 c = __ldcs(&x[i + 2 * stride]);
        i += 3 * stride;
        for (; i + 2 * stride < n4; i += 3 * stride) {
            float4 na = __ldcs(&x[i]);
            bin4(a, hl);
            float4 nb = __ldcs(&x[i + stride]);
            bin4(b, hl);
            float4 nc = __ldcs(&x[i + 2 * stride]);
            bin4(c, hl);
            a = na;
            b = nb;
            c = nc;
        }
        bin4(a, hl);
        bin4(b, hl);
        bin4(c, hl);
    }
    for (; i < n4; i += stride) {           // 0..2 leftover vectors
        float4 t = __ldcs(&x[i]);
        bin4(t, hl);
    }
    __syncthreads();

    // Reduce 32 lane-columns per bin. Diagonal read (start at own lane) keeps
    // all 32 lanes of a warp on distinct banks every step.
    if (threadIdx.x < BINS) {
        int b = threadIdx.x;
        unsigned int s = 0;
        #pragma unroll
        for (int k = 0; k < 32; k++)
            s += h[(b << 5) + ((k + lane) & 31)];
        if (s)
            atomicAdd(&g_partial[b], s);
    }

    // Last-block-done epilogue: final block writes both output copies and
    // resets scratch. Plain stores overwrite the harness poison.
    __threadfence();
    if (threadIdx.x == 0) {
        unsigned int t = atomicAdd(&g_ticket, 1u);
        is_last = (t == (unsigned int)gridDim.x - 1u);
    }
    __syncthreads();

    if (is_last && threadIdx.x < BINS) {
        int b = threadIdx.x;
        unsigned int v = atomicAdd(&g_partial[b], 0u);  // L2-coherent read
        float fv = (float)v;
        out[b] = fv;
        if (dup)
            out[b + BINS] = fv;
        g_partial[b] = 0u;      // reset for next graph replay
        if (b == 0)
            g_ticket = 0u;
    }
}

extern "C" void kernel_launch(void* const* d_in, const int* in_sizes, int n_in,
                              void* d_out, int out_size)
{
    const float4* x = (const float4*)d_in[0];
    float* out = (float*)d_out;
    int n4 = in_sizes[0] / 4;
    int dup = (out_size >= 2 * BINS) ? 1 : 0;

    histc_kernel<<<NBLOCKS, THREADS>>>(x, out, n4, dup);
}

// round 14
// speedup vs baseline: 1.3652x; 1.0288x over previous
#include <cuda_runtime.h>

#define THREADS 512
#define CTAS_PER_SM 3
#define BINS 256
#define HROWS 257               // row 256 catches x == +4.0 exactly (no IMIN)
#define NBLOCKS (148 * CTAS_PER_SM)  // 444 CTAs = exactly one wave at 3/SM

// Zero-initialized device scratch. The last block re-zeroes it every call, so
// every graph replay sees identical initial state (deterministic).
__device__ unsigned int g_partial[BINS];
__device__ unsigned int g_ticket;

// Histogram layout h[row][lane]: lane l only touches column l, so every
// warp-ATOMS hits 32 DISTINCT banks. Structurally conflict-free shared
// atomics (proven R7: L1% 63->33, dur 51.7->47.2).
__device__ __forceinline__ void bin_one(float f, unsigned int* hl) {
    // torch.histc: bins over [-4,4], x==4 -> last bin, outside ignored.
    // (f+4)*32 == fmaf(f,32,128) bit-exactly (x32 is an exact binade shift).
    // For |f|<=4 the raw index is 0..256; 256 occurs only for f==+4 and is
    // folded into bin 255 during the reduction -> no clamp in the hot path.
    if (fabsf(f) <= 4.0f) {
        int b = __float2int_rd(fmaf(f, 32.0f, 128.0f));
        atomicAdd(&hl[b << 5], 1u);   // hl already offset by lane
    }
}

__device__ __forceinline__ void bin4(float4 v, unsigned int* hl) {
    bin_one(v.x, hl);
    bin_one(v.y, hl);
    bin_one(v.z, hl);
    bin_one(v.w, hl);
}

__global__ __launch_bounds__(THREADS, CTAS_PER_SM) void histc_kernel(
    const float4* __restrict__ x, float* __restrict__ out, int n4, int dup)
{
    __shared__ unsigned int h[HROWS * 32];  // 32.9 KB: h[row*32 + lane]
    __shared__ bool is_last;

    #pragma unroll
    for (int i = threadIdx.x; i < HROWS * 32; i += THREADS)
        h[i] = 0u;
    __syncthreads();

    const int lane = threadIdx.x & 31;
    unsigned int* hl = &h[lane];

    const int stride = gridDim.x * blockDim.x;
    int i = blockIdx.x * blockDim.x + threadIdx.x;

    // Depth-4 cross-iteration pipeline at 48 warps/SM:
    //   48 warps x 4 LDG.128 x 4 lines = 192 outstanding lines < Q(~248),
    // same safe queue load as R8's 64x3x4, but more per-warp latency hiding.
    // (R4: 64x4x4=256 lines overflowed the queue -> 67us.)
    if (i + 3 * stride < n4) {
        float4 a = __ldcs(&x[i]);
        float4 b = __ldcs(&x[i + stride]);
        float4 c = __ldcs(&x[i + 2 * stride]);
        float4 d = __ldcs(&x[i + 3 * stride]);
        i += 4 * stride;
        for (; i + 3 * stride < n4; i += 4 * stride) {
            float4 na = __ldcs(&x[i]);
            bin4(a, hl);
            float4 nb = __ldcs(&x[i + stride]);
            bin4(b, hl);
            float4 nc = __ldcs(&x[i + 2 * stride]);
            bin4(c, hl);
            float4 nd = __ldcs(&x[i + 3 * stride]);
            bin4(d, hl);
            a = na;
            b = nb;
            c = nc;
            d = nd;
        }
        bin4(a, hl);
        bin4(b, hl);
        bin4(c, hl);
        bin4(d, hl);
    }
    for (; i < n4; i += stride) {           // 0..3 leftover vectors
        float4 t = __ldcs(&x[i]);
        bin4(t, hl);
    }
    __syncthreads();

    // Reduce 32 lane-columns per bin (diagonal read: all lanes on distinct
    // banks). Bin 255 additionally folds in row 256 (x == +4.0 exactly).
    if (threadIdx.x < BINS) {
        int b = threadIdx.x;
        unsigned int s = 0;
        #pragma unroll
        for (int k = 0; k < 32; k++)
            s += h[(b << 5) + ((k + lane) & 31)];
        if (b == BINS - 1) {
            #pragma unroll
            for (int k = 0; k < 32; k++)
                s += h[(BINS << 5) + k];
        }
        if (s)
            atomicAdd(&g_partial[b], s);
    }

    // Last-block-done epilogue: final block writes both output copies and
    // resets scratch. Plain stores overwrite the harness poison.
    __threadfence();
    if (threadIdx.x == 0) {
        unsigned int t = atomicAdd(&g_ticket, 1u);
        is_last = (t == (unsigned int)gridDim.x - 1u);
    }
    __syncthreads();

    if (is_last && threadIdx.x < BINS) {
        int b = threadIdx.x;
        unsigned int v = atomicAdd(&g_partial[b], 0u);  // L2-coherent read
        float fv = (float)v;
        out[b] = fv;
        if (dup)
            out[b + BINS] = fv;
        g_partial[b] = 0u;      // reset for next graph replay
        if (b == 0)
            g_ticket = 0u;
    }
}

extern "C" void kernel_launch(void* const* d_in, const int* in_sizes, int n_in,
                              void* d_out, int out_size)
{
    const float4* x = (const float4*)d_in[0];
    float* out = (float*)d_out;
    int n4 = in_sizes[0] / 4;
    int dup = (out_size >= 2 * BINS) ? 1 : 0;

    histc_kernel<<<NBLOCKS, THREADS>>>(x, out, n4, dup);
}